// round 17
// baseline (speedup 1.0000x reference)
#include <cuda_runtime.h>
#include <cuda_bf16.h>
#include <cstdint>

// Problem constants (fixed by the reference)
#define MAXN   50000
#define MPAD   50048            // padded to 128-row tiles
#define MAXE   800000
#define IN_F   256
#define HID    64
#define HEADS  4
#define OUT_F  64
#define F0     (HEADS*HID)   // 256
#define F1     OUT_F         // 64
#define NEG_SLOPE 0.2f

// ---------------- static scratch (no allocations allowed) ----------------
__device__ float g_h0  [(size_t)MAXN * F0];   // x @ W0^T
__device__ float g_h1  [(size_t)MAXN * F1];   // relu(agg0) @ W1^T
__device__ float g_e   [(size_t)MAXE * HEADS];// per-edge normalized alpha
__device__ float g_el  [(size_t)MAXN * HEADS];
__device__ float g_er  [(size_t)MAXN * HEADS];
__device__ int   g_cnt [MAXN];
__device__ int   g_rowptr[MAXN + 1];
__device__ int   g_wpos[MAXN];
__device__ int   g_srcsorted[MAXE];

// bf16 hi/lo operand copies; __align__(16) is REQUIRED for cp.async 16B sources
__device__ __align__(16) __nv_bfloat16 g_xhi [(size_t)MPAD * IN_F];
__device__ __align__(16) __nv_bfloat16 g_xlo [(size_t)MPAD * IN_F];
__device__ __align__(16) __nv_bfloat16 g_a0hi[(size_t)MPAD * F0];   // relu(agg0) split
__device__ __align__(16) __nv_bfloat16 g_a0lo[(size_t)MPAD * F0];
__device__ __align__(16) __nv_bfloat16 g_w0hi[F0 * IN_F];
__device__ __align__(16) __nv_bfloat16 g_w0lo[F0 * IN_F];
__device__ __align__(16) __nv_bfloat16 g_w1hi[F1 * F0];
__device__ __align__(16) __nv_bfloat16 g_w1lo[F1 * F0];

// ---------------- helpers ----------------
__device__ __forceinline__ void split2(float x, float y, uint32_t& hi, uint32_t& lo) {
    __nv_bfloat162 h = __floats2bfloat162_rn(x, y);
    __nv_bfloat162 l = __floats2bfloat162_rn(x - __bfloat162float(h.x),
                                             y - __bfloat162float(h.y));
    hi = *reinterpret_cast<uint32_t*>(&h);
    lo = *reinterpret_cast<uint32_t*>(&l);
}

__device__ __forceinline__ void mma16816(float* d, const uint32_t* a, const uint32_t* b) {
    asm volatile(
        "mma.sync.aligned.m16n8k16.row.col.f32.bf16.bf16.f32 "
        "{%0,%1,%2,%3}, {%4,%5,%6,%7}, {%8,%9}, {%0,%1,%2,%3};"
        : "+f"(d[0]), "+f"(d[1]), "+f"(d[2]), "+f"(d[3])
        : "r"(a[0]), "r"(a[1]), "r"(a[2]), "r"(a[3]), "r"(b[0]), "r"(b[1]));
}

#define CP16(dst, src) \
    asm volatile("cp.async.cg.shared.global [%0], [%1], 16;" \
                 :: "r"(dst), "l"(src) : "memory")
#define CP_COMMIT() asm volatile("cp.async.commit_group;" ::: "memory")
#define CP_WAIT1()  asm volatile("cp.async.wait_group 1;" ::: "memory")
#define CP_WAIT0()  asm volatile("cp.async.wait_group 0;" ::: "memory")

// ---------------- fp32 -> bf16 hi/lo split (once per operand) ----------------
__global__ void convert_split_kernel(const float* __restrict__ in,
                                     __nv_bfloat16* __restrict__ hi,
                                     __nv_bfloat16* __restrict__ lo, int n4) {
    int i = blockIdx.x * blockDim.x + threadIdx.x;
    if (i < n4) {
        float4 v = ((const float4*)in)[i];
        uint32_t h0, l0, h1, l1;
        split2(v.x, v.y, h0, l0);
        split2(v.z, v.w, h1, l1);
        ((uint2*)hi)[i] = make_uint2(h0, h1);
        ((uint2*)lo)[i] = make_uint2(l0, l1);
    }
}

// ---------------- CSR build ----------------
__global__ void count_kernel(const int* __restrict__ dst, int e) {
    int i = blockIdx.x * blockDim.x + threadIdx.x;
    if (i < e) atomicAdd(&g_cnt[dst[i]], 1);
}

__global__ void scan_kernel(int n) {
    __shared__ int warp_sums[32];
    const int tid  = threadIdx.x;
    const int lane = tid & 31;
    const int wid  = tid >> 5;
    int carry = 0;
    for (int base = 0; base < n; base += 1024) {
        int i = base + tid;
        int v = (i < n) ? g_cnt[i] : 0;
        int incl = v;
        #pragma unroll
        for (int o = 1; o < 32; o <<= 1) {
            int t = __shfl_up_sync(0xFFFFFFFFu, incl, o);
            if (lane >= o) incl += t;
        }
        if (lane == 31) warp_sums[wid] = incl;
        __syncthreads();
        if (wid == 0) {
            int x = warp_sums[lane];
            #pragma unroll
            for (int o = 1; o < 32; o <<= 1) {
                int t = __shfl_up_sync(0xFFFFFFFFu, x, o);
                if (lane >= o) x += t;
            }
            warp_sums[lane] = x;
        }
        __syncthreads();
        int off   = (wid > 0) ? warp_sums[wid - 1] : 0;
        int total = warp_sums[31];
        int excl  = carry + off + incl - v;
        if (i < n) { g_rowptr[i] = excl; g_wpos[i] = excl; }
        carry += total;
        __syncthreads();
    }
    if (tid == 0) g_rowptr[n] = carry;
}

__global__ void scatter_kernel(const int* __restrict__ src,
                               const int* __restrict__ dst, int e) {
    int i = blockIdx.x * blockDim.x + threadIdx.x;
    if (i < e) {
        int d = dst[i];
        int p = atomicAdd(&g_wpos[d], 1);
        g_srcsorted[p] = src[i];
    }
}

// ============ GEMM0: C[M,256] = x @ W0^T, cp.async double-buffered ============
// Block tile 128x128, warp tile 32x64 (one head per warp). bf16 hi/lo operands
// staged by cp.async; 3-term emulated fp32 MMA; register-only el/er epilogue.
__global__ __launch_bounds__(256)
void gemm0_cp_kernel(const __nv_bfloat16* __restrict__ Ahi,
                     const __nv_bfloat16* __restrict__ Alo,
                     const __nv_bfloat16* __restrict__ Bhi,
                     const __nv_bfloat16* __restrict__ Blo,
                     const float* __restrict__ al, const float* __restrict__ ar,
                     float* __restrict__ C,
                     float* __restrict__ el, float* __restrict__ er, int M) {
    constexpr int NOUT = F0, BN = 128, H = HEADS;
    constexpr int K = 256, KCH = 64, SREG = 36, JN = BN / 16;
    constexpr int AHI = 0, ALO = 128 * SREG;
    constexpr int BHI = 2 * 128 * SREG, BLO = BHI + BN * SREG;
    constexpr int BUFW = 4 * 128 * SREG;   // 18432 words per buffer

    extern __shared__ uint32_t sw[];
    const uint32_t sb = (uint32_t)__cvta_generic_to_shared(sw);
    const int tid  = threadIdx.x;
    const int wid  = tid >> 5;
    const int lane = tid & 31;
    const int tg   = lane >> 2;
    const int tig  = lane & 3;
    const int rowBase = blockIdx.x * 128;
    const int colBase = blockIdx.y * BN;
    const int wm = (wid & 3) * 32;
    const int wn = (wid >> 2) * (BN / 2);

    const int sr = tid >> 3;       // staging row (0..31 per it-step of 256 thr)
    const int sq = tid & 7;        // 16B quad within 128B row

    float acc[2][JN][4];
    #pragma unroll
    for (int i = 0; i < 2; i++)
        #pragma unroll
        for (int j = 0; j < JN; j++)
            #pragma unroll
            for (int q = 0; q < 4; q++) acc[i][j][q] = 0.f;

    // ---- stage chunk c into buffer buf (all via cp.async) ----
    auto stage = [&](int c, int buf) {
        const uint32_t db = sb + (uint32_t)buf * BUFW * 4;
        #pragma unroll
        for (int it = 0; it < 4; it++) {
            int r = sr + it * 32;
            size_t so = (size_t)(rowBase + r) * K + c * KCH + sq * 8;
            uint32_t dw = (uint32_t)(r * SREG + sq * 4) * 4;
            CP16(db + (AHI * 4) + dw, Ahi + so);
            CP16(db + (ALO * 4) + dw, Alo + so);
        }
        #pragma unroll
        for (int it = 0; it < 4; it++) {
            int r = sr + it * 32;
            size_t so = (size_t)(colBase + r) * K + c * KCH + sq * 8;
            uint32_t dw = (uint32_t)(r * SREG + sq * 4) * 4;
            CP16(db + (BHI * 4) + dw, Bhi + so);
            CP16(db + (BLO * 4) + dw, Blo + so);
        }
    };

    stage(0, 0);
    CP_COMMIT();

    for (int c = 0; c < K / KCH; c++) {
        const int buf = c & 1;
        if (c < K / KCH - 1) { stage(c + 1, 1 - buf); CP_COMMIT(); CP_WAIT1(); }
        else                 { CP_WAIT0(); }
        __syncthreads();

        const int bo = buf * BUFW;
        #pragma unroll
        for (int ks = 0; ks < KCH / 16; ks++) {
            const int kw = ks * 8;
            uint32_t ah[2][4], alr[2][4];
            #pragma unroll
            for (int i = 0; i < 2; i++) {
                int r0 = (wm + i * 16 + tg) * SREG + kw + tig;
                int r1 = r0 + 8 * SREG;
                ah[i][0]  = sw[bo + AHI + r0];     ah[i][1]  = sw[bo + AHI + r1];
                ah[i][2]  = sw[bo + AHI + r0 + 4]; ah[i][3]  = sw[bo + AHI + r1 + 4];
                alr[i][0] = sw[bo + ALO + r0];     alr[i][1] = sw[bo + ALO + r1];
                alr[i][2] = sw[bo + ALO + r0 + 4]; alr[i][3] = sw[bo + ALO + r1 + 4];
            }
            #pragma unroll
            for (int j = 0; j < JN; j++) {
                int n0 = (wn + j * 8 + tg) * SREG + kw + tig;
                uint32_t bhj[2] = { sw[bo + BHI + n0], sw[bo + BHI + n0 + 4] };
                uint32_t blj[2] = { sw[bo + BLO + n0], sw[bo + BLO + n0 + 4] };
                #pragma unroll
                for (int i = 0; i < 2; i++) {
                    mma16816(acc[i][j], ah[i],  bhj);
                    mma16816(acc[i][j], ah[i],  blj);
                    mma16816(acc[i][j], alr[i], bhj);
                }
            }
        }
        __syncthreads();
    }

    #pragma unroll
    for (int i = 0; i < 2; i++) {
        int r0 = rowBase + wm + i * 16 + tg;
        #pragma unroll
        for (int j = 0; j < JN; j++) {
            int col = colBase + wn + j * 8 + 2 * tig;
            if (r0 < M)
                *(float2*)(C + (size_t)r0 * NOUT + col)
                    = make_float2(acc[i][j][0], acc[i][j][1]);
            if (r0 + 8 < M)
                *(float2*)(C + (size_t)(r0 + 8) * NOUT + col)
                    = make_float2(acc[i][j][2], acc[i][j][3]);
        }
    }

    // register-only el/er epilogue (warp covers one head)
    {
        const int head = blockIdx.y * 2 + (wn >> 6);
        const float* alh = al + head * 64;
        const float* arh = ar + head * 64;
        #pragma unroll
        for (int i = 0; i < 2; i++) {
            float pl[2] = {0.f, 0.f}, pr[2] = {0.f, 0.f};
            #pragma unroll
            for (int j = 0; j < JN; j++) {
                int c0 = j * 8 + 2 * tig;
                float a0 = alh[c0], a1 = alh[c0 + 1];
                float r0 = arh[c0], r1 = arh[c0 + 1];
                pl[0] = fmaf(acc[i][j][0], a0, fmaf(acc[i][j][1], a1, pl[0]));
                pl[1] = fmaf(acc[i][j][2], a0, fmaf(acc[i][j][3], a1, pl[1]));
                pr[0] = fmaf(acc[i][j][0], r0, fmaf(acc[i][j][1], r1, pr[0]));
                pr[1] = fmaf(acc[i][j][2], r0, fmaf(acc[i][j][3], r1, pr[1]));
            }
            #pragma unroll
            for (int o = 1; o < 4; o <<= 1) {
                pl[0] += __shfl_xor_sync(0xFFFFFFFFu, pl[0], o);
                pl[1] += __shfl_xor_sync(0xFFFFFFFFu, pl[1], o);
                pr[0] += __shfl_xor_sync(0xFFFFFFFFu, pr[0], o);
                pr[1] += __shfl_xor_sync(0xFFFFFFFFu, pr[1], o);
            }
            if (tig == 0) {
                int gr = rowBase + wm + i * 16 + tg;
                if (gr < M) {
                    el[(size_t)gr * H + head] = pl[0];
                    er[(size_t)gr * H + head] = pr[0];
                }
                if (gr + 8 < M) {
                    el[(size_t)(gr + 8) * H + head] = pl[1];
                    er[(size_t)(gr + 8) * H + head] = pr[1];
                }
            }
        }
    }
}

// ============ GEMM1: C[M,64] = relu(agg0) @ W1^T, cp.async double-buffered ======
// A already relu'd + split by agg0. Block tile 128x64, warp tile 32x32.
__global__ __launch_bounds__(256)
void gemm1_cp_kernel(const __nv_bfloat16* __restrict__ Ahi,
                     const __nv_bfloat16* __restrict__ Alo,
                     const __nv_bfloat16* __restrict__ Bhi,
                     const __nv_bfloat16* __restrict__ Blo,
                     const float* __restrict__ al, const float* __restrict__ ar,
                     float* __restrict__ C,
                     float* __restrict__ el, float* __restrict__ er, int M) {
    constexpr int NOUT = F1;
    constexpr int K = 256, KCH = 64, SREG = 36;
    constexpr int AHI = 0, ALO = 128 * SREG;
    constexpr int BHI = 2 * 128 * SREG, BLO = BHI + 64 * SREG;
    constexpr int BUFW = (2 * 128 + 2 * 64) * SREG;   // 13824 words

    extern __shared__ uint32_t sw[];
    const uint32_t sb = (uint32_t)__cvta_generic_to_shared(sw);
    const int tid  = threadIdx.x;
    const int wid  = tid >> 5;
    const int lane = tid & 31;
    const int tg   = lane >> 2;
    const int tig  = lane & 3;
    const int rowBase = blockIdx.x * 128;
    const int wm = (wid & 3) * 32;
    const int wn = (wid >> 2) * 32;

    const int sr = tid >> 3;
    const int sq = tid & 7;

    float acc[2][4][4];
    #pragma unroll
    for (int i = 0; i < 2; i++)
        #pragma unroll
        for (int j = 0; j < 4; j++)
            #pragma unroll
            for (int q = 0; q < 4; q++) acc[i][j][q] = 0.f;

    auto stage = [&](int c, int buf) {
        const uint32_t db = sb + (uint32_t)buf * BUFW * 4;
        #pragma unroll
        for (int it = 0; it < 4; it++) {
            int r = sr + it * 32;
            size_t so = (size_t)(rowBase + r) * K + c * KCH + sq * 8;
            uint32_t dw = (uint32_t)(r * SREG + sq * 4) * 4;
            CP16(db + (AHI * 4) + dw, Ahi + so);
            CP16(db + (ALO * 4) + dw, Alo + so);
        }
        #pragma unroll
        for (int it = 0; it < 2; it++) {
            int r = sr + it * 32;
            size_t so = (size_t)r * K + c * KCH + sq * 8;
            uint32_t dw = (uint32_t)(r * SREG + sq * 4) * 4;
            CP16(db + (BHI * 4) + dw, Bhi + so);
            CP16(db + (BLO * 4) + dw, Blo + so);
        }
    };

    stage(0, 0);
    CP_COMMIT();

    for (int c = 0; c < K / KCH; c++) {
        const int buf = c & 1;
        if (c < K / KCH - 1) { stage(c + 1, 1 - buf); CP_COMMIT(); CP_WAIT1(); }
        else                 { CP_WAIT0(); }
        __syncthreads();

        const int bo = buf * BUFW;
        #pragma unroll
        for (int ks = 0; ks < KCH / 16; ks++) {
            const int kw = ks * 8;
            uint32_t ah[2][4], alr[2][4], bh[4][2], bl[4][2];
            #pragma unroll
            for (int i = 0; i < 2; i++) {
                int r0 = (wm + i * 16 + tg) * SREG + kw + tig;
                int r1 = r0 + 8 * SREG;
                ah[i][0]  = sw[bo + AHI + r0];     ah[i][1]  = sw[bo + AHI + r1];
                ah[i][2]  = sw[bo + AHI + r0 + 4]; ah[i][3]  = sw[bo + AHI + r1 + 4];
                alr[i][0] = sw[bo + ALO + r0];     alr[i][1] = sw[bo + ALO + r1];
                alr[i][2] = sw[bo + ALO + r0 + 4]; alr[i][3] = sw[bo + ALO + r1 + 4];
            }
            #pragma unroll
            for (int j = 0; j < 4; j++) {
                int n0 = (wn + j * 8 + tg) * SREG + kw + tig;
                bh[j][0] = sw[bo + BHI + n0]; bh[j][1] = sw[bo + BHI + n0 + 4];
                bl[j][0] = sw[bo + BLO + n0]; bl[j][1] = sw[bo + BLO + n0 + 4];
            }
            #pragma unroll
            for (int i = 0; i < 2; i++)
                #pragma unroll
                for (int j = 0; j < 4; j++) {
                    mma16816(acc[i][j], ah[i], bh[j]);
                    mma16816(acc[i][j], ah[i], bl[j]);
                    mma16816(acc[i][j], alr[i], bh[j]);
                }
        }
        __syncthreads();
    }

    #pragma unroll
    for (int i = 0; i < 2; i++) {
        int r0 = rowBase + wm + i * 16 + tg;
        #pragma unroll
        for (int j = 0; j < 4; j++) {
            int col = wn + j * 8 + 2 * tig;
            if (r0 < M)
                *(float2*)(C + (size_t)r0 * NOUT + col)
                    = make_float2(acc[i][j][0], acc[i][j][1]);
            if (r0 + 8 < M)
                *(float2*)(C + (size_t)(r0 + 8) * NOUT + col)
                    = make_float2(acc[i][j][2], acc[i][j][3]);
        }
    }

    // smem-combine el/er epilogue (H == 1)
    {
        float* elp = (float*)sw;
        float* erp = elp + 256;
        #pragma unroll
        for (int i = 0; i < 2; i++) {
            float pl[2] = {0.f, 0.f}, pr[2] = {0.f, 0.f};
            #pragma unroll
            for (int j = 0; j < 4; j++) {
                int c0 = wn + j * 8 + 2 * tig;
                float a0 = al[c0], a1 = al[c0 + 1];
                float r0 = ar[c0], r1 = ar[c0 + 1];
                pl[0] = fmaf(acc[i][j][0], a0, fmaf(acc[i][j][1], a1, pl[0]));
                pl[1] = fmaf(acc[i][j][2], a0, fmaf(acc[i][j][3], a1, pl[1]));
                pr[0] = fmaf(acc[i][j][0], r0, fmaf(acc[i][j][1], r1, pr[0]));
                pr[1] = fmaf(acc[i][j][2], r0, fmaf(acc[i][j][3], r1, pr[1]));
            }
            #pragma unroll
            for (int o = 1; o < 4; o <<= 1) {
                pl[0] += __shfl_xor_sync(0xFFFFFFFFu, pl[0], o);
                pl[1] += __shfl_xor_sync(0xFFFFFFFFu, pl[1], o);
                pr[0] += __shfl_xor_sync(0xFFFFFFFFu, pr[0], o);
                pr[1] += __shfl_xor_sync(0xFFFFFFFFu, pr[1], o);
            }
            if (tig == 0) {
                int half = wid >> 2;
                int r = wm + i * 16 + tg;
                elp[half * 128 + r]     = pl[0];
                erp[half * 128 + r]     = pr[0];
                elp[half * 128 + r + 8] = pl[1];
                erp[half * 128 + r + 8] = pr[1];
            }
        }
        __syncthreads();
        if (tid < 128) {
            int gr = rowBase + tid;
            if (gr < M) {
                el[gr] = elp[tid] + elp[128 + tid];
                er[gr] = erp[tid] + erp[128 + tid];
            }
        }
    }
}

// ---------------- per-dst-node softmax + aggregation (one warp / node) -------
// SPLIT=true (layer 0): output relu(acc+bias) pre-split to bf16 hi/lo.
template<int H, int D, bool SPLIT>
__global__ void agg_kernel(const float* __restrict__ Hm,
                           const float* __restrict__ el,
                           const float* __restrict__ er,
                           const float* __restrict__ bias,
                           float* __restrict__ out,
                           __nv_bfloat16* __restrict__ outHi,
                           __nv_bfloat16* __restrict__ outLo, int n) {
    const int F = H * D, PER = F / 32;
    int warp = threadIdx.x >> 5, lane = threadIdx.x & 31;
    int node = blockIdx.x * (blockDim.x >> 5) + warp;
    if (node >= n) return;

    const int start = g_rowptr[node];
    const int end   = g_rowptr[node + 1];

    float ern[H], mx[H], sm[H];
    #pragma unroll
    for (int h = 0; h < H; h++) {
        ern[h] = er[node * H + h];
        mx[h]  = -3.402823e38f;
        sm[h]  = 0.f;
    }

    for (int pos = start + lane; pos < end; pos += 32) {
        int s = g_srcsorted[pos];
        #pragma unroll
        for (int h = 0; h < H; h++) {
            float e = el[s * H + h] + ern[h];
            e = (e >= 0.f) ? e : NEG_SLOPE * e;
            float mn = fmaxf(mx[h], e);
            sm[h] = sm[h] * __expf(mx[h] - mn) + __expf(e - mn);
            mx[h] = mn;
        }
    }
    #pragma unroll
    for (int h = 0; h < H; h++) {
        #pragma unroll
        for (int o = 16; o > 0; o >>= 1) {
            float mo = __shfl_xor_sync(0xFFFFFFFFu, mx[h], o);
            float so = __shfl_xor_sync(0xFFFFFFFFu, sm[h], o);
            float mn = fmaxf(mx[h], mo);
            sm[h] = sm[h] * __expf(mx[h] - mn) + so * __expf(mo - mn);
            mx[h] = mn;
        }
    }

    float rcp[H];
    #pragma unroll
    for (int h = 0; h < H; h++) rcp[h] = (sm[h] > 0.f) ? (1.f / sm[h]) : 0.f;

    for (int pos = start + lane; pos < end; pos += 32) {
        int s = g_srcsorted[pos];
        #pragma unroll
        for (int h = 0; h < H; h++) {
            float e = el[s * H + h] + ern[h];
            e = (e >= 0.f) ? e : NEG_SLOPE * e;
            g_e[(size_t)pos * H + h] = __expf(e - mx[h]) * rcp[h];
        }
    }
    __syncwarp();

    const int hd = (lane * PER) / D;

    float acc[PER];
    #pragma unroll
    for (int j = 0; j < PER; j++) acc[j] = 0.f;

    for (int pos = start; pos < end; pos++) {
        float a = g_e[(size_t)pos * H + hd];
        int   s = g_srcsorted[pos];
        if constexpr (PER == 8) {
            const float4* hp = (const float4*)(Hm + (size_t)s * F) + lane * 2;
            float4 v0 = hp[0], v1 = hp[1];
            acc[0] = fmaf(a, v0.x, acc[0]); acc[1] = fmaf(a, v0.y, acc[1]);
            acc[2] = fmaf(a, v0.z, acc[2]); acc[3] = fmaf(a, v0.w, acc[3]);
            acc[4] = fmaf(a, v1.x, acc[4]); acc[5] = fmaf(a, v1.y, acc[5]);
            acc[6] = fmaf(a, v1.z, acc[6]); acc[7] = fmaf(a, v1.w, acc[7]);
        } else {
            const float2* hp = (const float2*)(Hm + (size_t)s * F) + lane;
            float2 v = hp[0];
            acc[0] = fmaf(a, v.x, acc[0]);
            acc[1] = fmaf(a, v.y, acc[1]);
        }
    }

    if constexpr (SPLIT) {
        // relu(acc + bias), split to bf16 hi/lo, 16B vector stores
        uint32_t ph[4], pq[4];
        #pragma unroll
        for (int j2 = 0; j2 < 4; j2++) {
            float o0 = fmaxf(acc[2 * j2]     + bias[lane * PER + 2 * j2],     0.f);
            float o1 = fmaxf(acc[2 * j2 + 1] + bias[lane * PER + 2 * j2 + 1], 0.f);
            split2(o0, o1, ph[j2], pq[j2]);
        }
        *(uint4*)(outHi + (size_t)node * F + lane * PER) = *(uint4*)ph;
        *(uint4*)(outLo + (size_t)node * F + lane * PER) = *(uint4*)pq;
    } else {
        #pragma unroll
        for (int j = 0; j < PER; j++)
            out[(size_t)node * F + lane * PER + j] = acc[j] + bias[lane * PER + j];
    }
}

// ---------------- launch ----------------
extern "C" void kernel_launch(void* const* d_in, const int* in_sizes, int n_in,
                              void* d_out, int out_size) {
    const float* x   = (const float*)d_in[0];
    const int*   src = (const int*)  d_in[1];
    const int*   dst = (const int*)  d_in[2];
    const float* W0  = (const float*)d_in[3];
    const float* al0 = (const float*)d_in[4];
    const float* ar0 = (const float*)d_in[5];
    const float* b0  = (const float*)d_in[6];
    const float* W1  = (const float*)d_in[7];
    const float* al1 = (const float*)d_in[8];
    const float* ar1 = (const float*)d_in[9];
    const float* b1  = (const float*)d_in[10];
    float* out = (float*)d_out;

    int n = in_sizes[0] / IN_F;
    int e = in_sizes[1];
    if (n > MAXN) n = MAXN;
    if (e > MAXE) e = MAXE;

    float *h0, *h1, *elp, *erp;
    int   *cntp;
    __nv_bfloat16 *xhi, *xlo, *a0hi, *a0lo, *w0hi, *w0lo, *w1hi, *w1lo;
    cudaGetSymbolAddress((void**)&h0,   g_h0);
    cudaGetSymbolAddress((void**)&h1,   g_h1);
    cudaGetSymbolAddress((void**)&elp,  g_el);
    cudaGetSymbolAddress((void**)&erp,  g_er);
    cudaGetSymbolAddress((void**)&cntp, g_cnt);
    cudaGetSymbolAddress((void**)&xhi,  g_xhi);
    cudaGetSymbolAddress((void**)&xlo,  g_xlo);
    cudaGetSymbolAddress((void**)&a0hi, g_a0hi);
    cudaGetSymbolAddress((void**)&a0lo, g_a0lo);
    cudaGetSymbolAddress((void**)&w0hi, g_w0hi);
    cudaGetSymbolAddress((void**)&w0lo, g_w0lo);
    cudaGetSymbolAddress((void**)&w1hi, g_w1hi);
    cudaGetSymbolAddress((void**)&w1lo, g_w1lo);

    const int SMEM0 = 2 * 4 * 128 * 36 * 4;             // 147456 (double buffer)
    const int SMEM1 = 2 * (2 * 128 + 2 * 64) * 36 * 4;  // 110592
    cudaFuncSetAttribute(gemm0_cp_kernel,
                         cudaFuncAttributeMaxDynamicSharedMemorySize, SMEM0);
    cudaFuncSetAttribute(gemm1_cp_kernel,
                         cudaFuncAttributeMaxDynamicSharedMemorySize, SMEM1);

    static cudaStream_t s2 = nullptr;
    static cudaEvent_t evFork = nullptr, evW = nullptr, evJoin = nullptr;
    if (s2 == nullptr) {
        cudaStreamCreateWithFlags(&s2, cudaStreamNonBlocking);
        cudaEventCreateWithFlags(&evFork, cudaEventDisableTiming);
        cudaEventCreateWithFlags(&evW,    cudaEventDisableTiming);
        cudaEventCreateWithFlags(&evJoin, cudaEventDisableTiming);
    }

    const int TB = 256;
    int gtiles = (n + 127) / 128;

    // ---- fork: weight converts + CSR build on s2 ----
    cudaEventRecord(evFork, 0);
    cudaStreamWaitEvent(s2, evFork, 0);

    convert_split_kernel<<<(F0 * IN_F / 4 + TB - 1) / TB, TB, 0, s2>>>(
        W0, w0hi, w0lo, F0 * IN_F / 4);
    convert_split_kernel<<<(F1 * F0 / 4 + TB - 1) / TB, TB, 0, s2>>>(
        W1, w1hi, w1lo, F1 * F0 / 4);
    cudaEventRecord(evW, s2);

    cudaMemsetAsync(cntp, 0, (size_t)n * sizeof(int), s2);
    count_kernel  <<<(e + TB - 1) / TB, TB, 0, s2>>>(dst, e);
    scan_kernel   <<<1, 1024, 0, s2>>>(n);
    scatter_kernel<<<(e + TB - 1) / TB, TB, 0, s2>>>(src, dst, e);
    cudaEventRecord(evJoin, s2);

    // ---- main: convert x, then GEMM0 (needs w0 converts) ----
    convert_split_kernel<<<((n * IN_F / 4) + TB - 1) / TB, TB>>>(
        x, xhi, xlo, n * IN_F / 4);
    cudaStreamWaitEvent(0, evW, 0);
    gemm0_cp_kernel<<<dim3(gtiles, F0 / 128), 256, SMEM0>>>(
        xhi, xlo, w0hi, w0lo, al0, ar0, h0, elp, erp, n);

    // ---- join: agg0 needs GEMM0 + CSR; outputs relu+split bf16 ----
    cudaStreamWaitEvent(0, evJoin, 0);
    agg_kernel<HEADS, HID, true><<<(n + 7) / 8, 256>>>(
        h0, elp, erp, b0, nullptr, a0hi, a0lo, n);

    // ---- layer 1 ----
    gemm1_cp_kernel<<<gtiles, 256, SMEM1>>>(
        a0hi, a0lo, w1hi, w1lo, al1, ar1, h1, elp, erp, n);
    agg_kernel<1, OUT_F, false><<<(n + 7) / 8, 256>>>(
        h1, elp, erp, b1, out, nullptr, nullptr, n);
}